// round 4
// baseline (speedup 1.0000x reference)
#include <cuda_runtime.h>

// Fully fused ContrastiveLoss: one block, one launch.
// R4: phases 1/3 software-pipelined — 8 sids prefetched into registers per
// lane (8 independent coalesced LDG.64s -> MLP=8) before the match rounds.
// Element->lane mapping (i = base + k*32 + lane) unchanged, so order-
// preserving ranks are identical to the R3-verified logic.

#define NSUBJ 1024
#define NWARP 32
#define MAXP 50
#define CAP 51   // max occurrence indices per subject the enumeration can touch
#define ROUNDS 8 // prefetch depth (elements per lane per outer iteration)

#define WCNT_B (NSUBJ * NWARP * 2)        // 65536
#define SIDX_B (NSUBJ * CAP * 2)          // 104448
#define SCNT_B (NSUBJ * 4)                // 4096
#define SMEM_TOTAL (WCNT_B + SIDX_B + SCNT_B + 2 * MAXP * 2 * 4 + 8 + 128)

// subject_ids may be int64 or (jax x64-off) int32. 16 consecutive int64 reads
// all in [0, NSUBJ) <=> genuinely int64.
__device__ __forceinline__ bool detect64(const void* p) {
    const long long* q = (const long long*)p;
    bool ok = true;
#pragma unroll
    for (int k = 0; k < 16; k++) {
        long long v = q[k];
        ok = ok && (v >= 0 && v < (long long)NSUBJ);
    }
    return ok;
}

__device__ __forceinline__ long long sid_or_neg(const void* p, int i, int B, bool is64) {
    if (i >= B) return -1ll;
    return is64 ? ((const long long*)p)[i] : (long long)((const int*)p)[i];
}

__global__ void __launch_bounds__(1024, 1)
fused_contrastive(const void* __restrict__ sids, const float* __restrict__ x,
                  float* __restrict__ out, int B, int D) {
    extern __shared__ unsigned char sm[];
    unsigned short* wcnt = (unsigned short*)sm;                       // [s*32+w]
    unsigned short* sidx = (unsigned short*)(sm + WCNT_B);            // [s*CAP+slot]
    int* scnt = (int*)(sm + WCNT_B + SIDX_B);                         // [s]
    int* ii   = scnt + NSUBJ;                                         // pos [0..MAXP), neg [MAXP..2*MAXP)
    int* jj   = ii + 2 * MAXP;
    int* npn  = jj + 2 * MAXP;                                        // {npos, nneg}
    float* part = (float*)(npn + 2);                                  // [32]

    const int tid = threadIdx.x, lane = tid & 31, w = tid >> 5;
    const bool is64 = detect64(sids);

    // zero wcnt (as u32 words)
    {
        unsigned int* z = (unsigned int*)wcnt;
        for (int k = tid; k < WCNT_B / 4; k += 1024) z[k] = 0u;
    }
    __syncthreads();

    // warp w owns contiguous element range [w*iters*32, (w+1)*iters*32)
    const int iters = (B + NWARP * 32 - 1) / (NWARP * 32);
    const int base = w * iters * 32;

    // ---- Phase 1: counts per (subject, warp), 8-deep prefetch ----
    {
        int k = 0;
        for (; k + ROUNDS <= iters; k += ROUNDS) {
            long long v[ROUNDS];
#pragma unroll
            for (int r = 0; r < ROUNDS; r++)
                v[r] = sid_or_neg(sids, base + (k + r) * 32 + lane, B, is64);
#pragma unroll
            for (int r = 0; r < ROUNDS; r++) {
                bool valid = v[r] >= 0;
                int s = valid ? (int)v[r] : 0;
                int key = valid ? s : (NSUBJ + lane);
                unsigned mask = __match_any_sync(0xFFFFFFFFu, key);
                if (valid && lane == (__ffs(mask) - 1))
                    wcnt[s * NWARP + w] = (unsigned short)(wcnt[s * NWARP + w] + __popc(mask));
            }
        }
        for (; k < iters; k++) {                       // tail (B not multiple of 8192)
            long long v = sid_or_neg(sids, base + k * 32 + lane, B, is64);
            bool valid = v >= 0;
            int s = valid ? (int)v : 0;
            int key = valid ? s : (NSUBJ + lane);
            unsigned mask = __match_any_sync(0xFFFFFFFFu, key);
            if (valid && lane == (__ffs(mask) - 1))
                wcnt[s * NWARP + w] = (unsigned short)(wcnt[s * NWARP + w] + __popc(mask));
        }
    }
    __syncthreads();

    // ---- Phase 2: per-subject exclusive prefix over warps ----
    {
        int s = tid;  // blockDim == 1024 == NSUBJ
        int run = 0;
#pragma unroll
        for (int c = 0; c < NWARP; c++) {
            int v = wcnt[s * NWARP + c];
            wcnt[s * NWARP + c] = (unsigned short)run;
            run += v;
        }
        scnt[s] = run;
    }
    __syncthreads();

    // ---- Phase 3: order-preserving scatter of first CAP indices, 8-deep prefetch ----
    {
        int k = 0;
        for (; k + ROUNDS <= iters; k += ROUNDS) {
            long long v[ROUNDS];
#pragma unroll
            for (int r = 0; r < ROUNDS; r++)
                v[r] = sid_or_neg(sids, base + (k + r) * 32 + lane, B, is64);
#pragma unroll
            for (int r = 0; r < ROUNDS; r++) {
                int i = base + (k + r) * 32 + lane;
                bool valid = v[r] >= 0;
                int s = valid ? (int)v[r] : 0;
                int key = valid ? s : (NSUBJ + lane);
                unsigned mask = __match_any_sync(0xFFFFFFFFu, key);
                if (valid) {
                    int rank = __popc(mask & ((1u << lane) - 1u));
                    int cur = wcnt[s * NWARP + w];       // all lanes read before leader's store
                    int slot = cur + rank;
                    if (lane == (__ffs(mask) - 1))
                        wcnt[s * NWARP + w] = (unsigned short)(cur + __popc(mask));
                    if (slot < CAP) sidx[s * CAP + slot] = (unsigned short)i;
                }
            }
        }
        for (; k < iters; k++) {
            int i = base + k * 32 + lane;
            long long v = sid_or_neg(sids, i, B, is64);
            bool valid = v >= 0;
            int s = valid ? (int)v : 0;
            int key = valid ? s : (NSUBJ + lane);
            unsigned mask = __match_any_sync(0xFFFFFFFFu, key);
            if (valid) {
                int rank = __popc(mask & ((1u << lane) - 1u));
                int cur = wcnt[s * NWARP + w];
                int slot = cur + rank;
                if (lane == (__ffs(mask) - 1))
                    wcnt[s * NWARP + w] = (unsigned short)(cur + __popc(mask));
                if (slot < CAP) sidx[s * CAP + slot] = (unsigned short)i;
            }
        }
    }
    __syncthreads();

    // ---- Phase 4: exact replica of reference pair enumeration (thread 0, all smem) ----
    if (tid == 0) {
        int npos = 0, nneg = 0;
        for (int s = 0; s < NSUBJ; s++) {
            int cs = scnt[s];
            if (cs == 0) continue;                       // uniq membership (sorted ascending)
            int til = cs < CAP ? cs : CAP;
            if (cs >= 2 && npos < MAXP) {
                for (int a = 0; a < til && npos < MAXP; a++)
                    for (int b = a + 1; b < til && npos < MAXP; b++) {
                        ii[npos] = sidx[s * CAP + a];
                        jj[npos] = sidx[s * CAP + b];
                        npos++;
                    }
            }
            for (int o = 0; o < NSUBJ; o++) {
                int co = scnt[o];
                if (co == 0) continue;
                if (o == s) continue;                    // python: continue precedes break check
                if (nneg >= MAXP) break;
                int tjl = co < CAP ? co : CAP;
                for (int a = 0; a < til && nneg < MAXP; a++)
                    for (int b = 0; b < tjl && nneg < MAXP; b++) {
                        ii[MAXP + nneg] = sidx[s * CAP + a];
                        jj[MAXP + nneg] = sidx[o * CAP + b];
                        nneg++;
                    }
            }
            if (npos >= MAXP && nneg >= MAXP) break;
        }
        npn[0] = npos;
        npn[1] = nneg;
    }
    __syncthreads();

    // ---- Phase 5: warp-per-pair normalized dot + stable BCE ----
    const int npos = npn[0], nneg = npn[1], n = npos + nneg;
    float acc = 0.0f;
    const int nvec = D / 4;                              // D=384 -> 96 float4
    for (int p = w; p < n; p += NWARP) {
        int slot = (p < npos) ? p : (MAXP + (p - npos));
        int i = ii[slot], j = jj[slot];
        const float4* xi = (const float4*)(x + (long long)i * D);
        const float4* xj = (const float4*)(x + (long long)j * D);
        float sxx = 0.f, syy = 0.f, sxy = 0.f;
        for (int q = lane; q < nvec; q += 32) {
            float4 a = xi[q];
            float4 b = xj[q];
            sxx += a.x * a.x + a.y * a.y + a.z * a.z + a.w * a.w;
            syy += b.x * b.x + b.y * b.y + b.z * b.z + b.w * b.w;
            sxy += a.x * b.x + a.y * b.y + a.z * b.z + a.w * b.w;
        }
#pragma unroll
        for (int off = 16; off; off >>= 1) {
            sxx += __shfl_xor_sync(0xFFFFFFFFu, sxx, off);
            syy += __shfl_xor_sync(0xFFFFFFFFu, syy, off);
            sxy += __shfl_xor_sync(0xFFFFFFFFu, sxy, off);
        }
        // every lane now holds the full sums; acc is replicated across lanes
        float ni = fmaxf(sqrtf(sxx), 1e-12f);
        float nj = fmaxf(sqrtf(syy), 1e-12f);
        float sc = (sxy / (ni * nj)) * 2.0f;             // / TEMPERATURE (0.5)
        float xs = (p < npos) ? -sc : sc;
        acc += fmaxf(xs, 0.f) + log1pf(expf(-fabsf(xs)));  // softplus(xs)
    }

    // acc is identical on all lanes -> lane 0's copy IS the warp partial
    if (lane == 0) part[w] = acc;
    __syncthreads();
    if (w == 0) {
        float v = part[lane];
#pragma unroll
        for (int off = 16; off; off >>= 1) v += __shfl_xor_sync(0xFFFFFFFFu, v, off);
        if (lane == 0) out[0] = v / (float)n;
    }
}

extern "C" void kernel_launch(void* const* d_in, const int* in_sizes, int n_in,
                              void* d_out, int out_size) {
    const float* x = (const float*)d_in[0];   // identity_tokens [B, D] fp32
    const void* sids = d_in[1];               // subject_ids [B]
    int B = in_sizes[1];
    int D = in_sizes[0] / B;

    cudaFuncSetAttribute(fused_contrastive,
                         cudaFuncAttributeMaxDynamicSharedMemorySize, SMEM_TOTAL);

    fused_contrastive<<<1, 1024, SMEM_TOTAL>>>(sids, x, (float*)d_out, B, D);
}

// round 5
// speedup vs baseline: 4.5191x; 4.5191x over previous
#include <cuda_runtime.h>

// Multi-SM fused ContrastiveLoss, one launch, grid=64 blocks + global barrier.
// A: per-block order-preserving counting (1 elem/thread, warp __match_any_sync,
//    cross-warp smem prefix) -> per-(block,subject) counts in global [blk][subj].
// B: per-subject cross-block prefix (thread s scans its column; coalesced).
// C: scatter first CAP indices per subject to global g_gidx.
// D: block 0 mirrors g_gidx to smem, thread 0 replicates the exact reference
//    pair enumeration, then 32 warps do normalized-dot + stable-BCE loss.

#define NSUBJ 1024
#define NWARP 32
#define MAXP 50
#define CAP 51
#define GRID 64
#define T 1024

#define WCNT_B (NSUBJ * NWARP * 2)       // 65536 (phase A, aliases idx mirror)
#define IDXM_B (NSUBJ * CAP * 4)         // 208896 (phase D mirror)
#define SMEM_TOTAL (IDXM_B + 4096 /*scnt*/ + 4096 /*off*/ + 2*MAXP*4*2 + 8 + 128 + 64)

__device__ unsigned g_bar_count = 0;
__device__ unsigned g_bar_sense = 0;
__device__ unsigned g_bcnt[GRID * NSUBJ];   // [block][subject]
__device__ unsigned g_gidx[NSUBJ * CAP];    // [subject][slot]

// subject_ids may be int64 or (jax x64-off) int32.
__device__ __forceinline__ bool detect64(const void* p) {
    const long long* q = (const long long*)p;
    bool ok = true;
#pragma unroll
    for (int k = 0; k < 16; k++) {
        long long v = q[k];
        ok = ok && (v >= 0 && v < (long long)NSUBJ);
    }
    return ok;
}

__device__ __forceinline__ long long sid_or_neg(const void* p, int i, int B, bool is64) {
    if (i >= B) return -1ll;
    return is64 ? ((const long long*)p)[i] : (long long)((const int*)p)[i];
}

// Sense-reversing global barrier (all GRID blocks resident; graph-replay safe:
// leaves count=0, sense toggled and re-read at each barrier entry).
__device__ __forceinline__ void gbar() {
    __syncthreads();
    if (threadIdx.x == 0) {
        __threadfence();
        unsigned my = atomicOr(&g_bar_sense, 0u);          // read current sense
        if (atomicAdd(&g_bar_count, 1u) == GRID - 1) {
            atomicExch(&g_bar_count, 0u);
            __threadfence();
            atomicExch(&g_bar_sense, my ^ 1u);
        } else {
            while (atomicOr(&g_bar_sense, 0u) == my) __nanosleep(64);
        }
        __threadfence();
    }
    __syncthreads();
}

__global__ void __launch_bounds__(T, 1)
fused_contrastive(const void* __restrict__ sids, const float* __restrict__ x,
                  float* __restrict__ out, int B, int D) {
    extern __shared__ unsigned char sm[];
    unsigned short* wc  = (unsigned short*)sm;             // [s*32+w], phase A/C
    unsigned int* idxm  = (unsigned int*)sm;               // [s*CAP+slot], phase D
    int* scnt = (int*)(sm + IDXM_B);                       // [s] totals (block 0)
    int* off  = scnt + NSUBJ;                              // [s] cross-block excl offset
    int* ii   = off + NSUBJ;                               // pos [0..MAXP), neg [MAXP..)
    int* jj   = ii + 2 * MAXP;
    int* npn  = jj + 2 * MAXP;
    float* part = (float*)(npn + 2);                       // [32]

    const int tid = threadIdx.x, lane = tid & 31, w = tid >> 5;
    const int b = blockIdx.x;
    const bool is64 = detect64(sids);

    const int e = (B + GRID * T - 1) / (GRID * T);         // elements per thread (1 here)
    const int base = b * e * T + w * e * 32;               // warp-contiguous range

    // zero wc
    {
        unsigned int* z = (unsigned int*)wc;
        for (int k = tid; k < WCNT_B / 4; k += T) z[k] = 0u;
    }
    __syncthreads();

    // ---- A1: per-(subject,warp) counts within block ----
    for (int k = 0; k < e; k++) {
        long long v = sid_or_neg(sids, base + k * 32 + lane, B, is64);
        bool valid = v >= 0;
        int s = valid ? (int)v : 0;
        int key = valid ? s : (NSUBJ + lane);
        unsigned mask = __match_any_sync(0xFFFFFFFFu, key);
        if (valid && lane == (__ffs(mask) - 1))
            wc[s * NWARP + w] = (unsigned short)(wc[s * NWARP + w] + __popc(mask));
    }
    __syncthreads();

    // ---- A2: thread s: block-local exclusive prefix over warps; publish count ----
    {
        int s = tid;
        int run = 0;
#pragma unroll
        for (int c = 0; c < NWARP; c++) {
            int v = wc[s * NWARP + c];
            wc[s * NWARP + c] = (unsigned short)run;
            run += v;
        }
        g_bcnt[b * NSUBJ + s] = (unsigned)run;             // coalesced
    }

    gbar();

    // ---- B: thread s: cross-block prefix for its subject (coalesced column) ----
    {
        int s = tid;
        int pre = 0, tot = 0;
#pragma unroll 16
        for (int c = 0; c < GRID; c++) {
            int u = (int)g_bcnt[c * NSUBJ + s];
            tot += u;
            if (c < b) pre += u;
        }
        off[s] = pre;
        if (b == 0) scnt[s] = tot;
    }
    __syncthreads();

    // ---- C: order-preserving scatter of first CAP indices to global ----
    for (int k = 0; k < e; k++) {
        int i = base + k * 32 + lane;
        long long v = sid_or_neg(sids, i, B, is64);
        bool valid = v >= 0;
        int s = valid ? (int)v : 0;
        int key = valid ? s : (NSUBJ + lane);
        unsigned mask = __match_any_sync(0xFFFFFFFFu, key);
        if (valid) {
            int rank = __popc(mask & ((1u << lane) - 1u));
            int cur = wc[s * NWARP + w];                   // all lanes read before leader store
            int slot = off[s] + cur + rank;
            if (lane == (__ffs(mask) - 1))
                wc[s * NWARP + w] = (unsigned short)(cur + __popc(mask));
            if (slot < CAP) g_gidx[s * CAP + slot] = (unsigned)i;
        }
    }

    gbar();
    if (b != 0) return;

    // ---- D0: mirror g_gidx into smem (overwrites dead wc region) ----
    for (int k = tid; k < NSUBJ * CAP; k += T) idxm[k] = g_gidx[k];
    __syncthreads();

    // ---- D1: exact replica of reference pair enumeration (thread 0, all smem) ----
    if (tid == 0) {
        int npos = 0, nneg = 0;
        for (int s = 0; s < NSUBJ; s++) {
            int cs = scnt[s];
            if (cs == 0) continue;                         // uniq (sorted ascending)
            int til = cs < CAP ? cs : CAP;
            if (cs >= 2 && npos < MAXP) {
                for (int a = 0; a < til && npos < MAXP; a++)
                    for (int bb = a + 1; bb < til && npos < MAXP; bb++) {
                        ii[npos] = (int)idxm[s * CAP + a];
                        jj[npos] = (int)idxm[s * CAP + bb];
                        npos++;
                    }
            }
            for (int o = 0; o < NSUBJ; o++) {
                int co = scnt[o];
                if (co == 0) continue;
                if (o == s) continue;                      // python: continue precedes break
                if (nneg >= MAXP) break;
                int tjl = co < CAP ? co : CAP;
                for (int a = 0; a < til && nneg < MAXP; a++)
                    for (int bb = 0; bb < tjl && nneg < MAXP; bb++) {
                        ii[MAXP + nneg] = (int)idxm[s * CAP + a];
                        jj[MAXP + nneg] = (int)idxm[o * CAP + bb];
                        nneg++;
                    }
            }
            if (npos >= MAXP && nneg >= MAXP) break;
        }
        npn[0] = npos;
        npn[1] = nneg;
    }
    __syncthreads();

    // ---- D2: warp-per-pair normalized dot + stable BCE ----
    const int npos = npn[0], nneg = npn[1], n = npos + nneg;
    float acc = 0.0f;
    const int nvec = D / 4;                                // D=384 -> 96 float4
    for (int p = w; p < n; p += NWARP) {
        int slot = (p < npos) ? p : (MAXP + (p - npos));
        int i = ii[slot], j = jj[slot];
        const float4* xi = (const float4*)(x + (long long)i * D);
        const float4* xj = (const float4*)(x + (long long)j * D);
        float sxx = 0.f, syy = 0.f, sxy = 0.f;
        for (int q = lane; q < nvec; q += 32) {
            float4 a = xi[q];
            float4 bq = xj[q];
            sxx += a.x * a.x + a.y * a.y + a.z * a.z + a.w * a.w;
            syy += bq.x * bq.x + bq.y * bq.y + bq.z * bq.z + bq.w * bq.w;
            sxy += a.x * bq.x + a.y * bq.y + a.z * bq.z + a.w * bq.w;
        }
#pragma unroll
        for (int o = 16; o; o >>= 1) {
            sxx += __shfl_xor_sync(0xFFFFFFFFu, sxx, o);
            syy += __shfl_xor_sync(0xFFFFFFFFu, syy, o);
            sxy += __shfl_xor_sync(0xFFFFFFFFu, sxy, o);
        }
        float ni = fmaxf(sqrtf(sxx), 1e-12f);
        float nj = fmaxf(sqrtf(syy), 1e-12f);
        float sc = (sxy / (ni * nj)) * 2.0f;               // / TEMPERATURE (0.5)
        float xs = (p < npos) ? -sc : sc;
        acc += fmaxf(xs, 0.f) + log1pf(expf(-fabsf(xs))); // softplus(xs)
    }

    // acc is replicated across lanes -> lane 0's copy IS the warp partial
    if (lane == 0) part[w] = acc;
    __syncthreads();
    if (w == 0) {
        float v = part[lane];
#pragma unroll
        for (int o = 16; o; o >>= 1) v += __shfl_xor_sync(0xFFFFFFFFu, v, o);
        if (lane == 0) out[0] = v / (float)n;
    }
}

extern "C" void kernel_launch(void* const* d_in, const int* in_sizes, int n_in,
                              void* d_out, int out_size) {
    const float* x = (const float*)d_in[0];   // identity_tokens [B, D] fp32
    const void* sids = d_in[1];               // subject_ids [B]
    int B = in_sizes[1];
    int D = in_sizes[0] / B;

    cudaFuncSetAttribute(fused_contrastive,
                         cudaFuncAttributeMaxDynamicSharedMemorySize, SMEM_TOTAL);

    fused_contrastive<<<GRID, T, SMEM_TOTAL>>>(sids, x, (float*)d_out, B, D);
}

// round 6
// speedup vs baseline: 6.3503x; 1.4052x over previous
#include <cuda_runtime.h>

// Multi-SM fused ContrastiveLoss, one launch, grid=64 + one global barrier.
// A: per-block order-preserving counting (warp __match_any_sync, cross-warp
//    smem prefix) -> per-(block,subject) counts in global [blk][subj].
// B: per-subject cross-block prefix (thread s scans its column; all blocks
//    also compute the per-subject totals -> scnt lives in every block's smem).
// C: scatter first CAP global indices per subject to g_gidx; arrive & exit.
// D: blocks 0..NLOSS-1 spin on arrival counter, redundantly run the exact
//    reference pair enumeration (smem-only, pairs stored as encoded
//    subject*CAP+slot handles), each computes loss for pairs p%NLOSS==r,
//    float-atomicAdd partials; last block writes out and resets replay state.

#define NSUBJ 1024
#define NWARP 32
#define MAXP 50
#define CAP 51
#define GRID 64
#define T 1024
#define NLOSS 4

#define WCNT_B (NSUBJ * NWARP * 2)       // 65536
#define SMEM_TOTAL (WCNT_B + 4096 /*scnt*/ + 4096 /*off*/ + 2*MAXP*4*2 + 16 + 128 + 64)

__device__ unsigned g_bar_count = 0;
__device__ unsigned g_bar_sense = 0;
__device__ unsigned g_done = 0;             // phase-C arrival counter
__device__ unsigned g_ldone = 0;            // loss-block completion counter
__device__ float    g_acc = 0.0f;           // loss partial accumulator
__device__ unsigned g_bcnt[GRID * NSUBJ];   // [block][subject]
__device__ unsigned g_gidx[NSUBJ * CAP];    // [subject][slot]

// subject_ids may be int64 or (jax x64-off) int32.
__device__ __forceinline__ bool detect64(const void* p) {
    const long long* q = (const long long*)p;
    bool ok = true;
#pragma unroll
    for (int k = 0; k < 16; k++) {
        long long v = q[k];
        ok = ok && (v >= 0 && v < (long long)NSUBJ);
    }
    return ok;
}

__device__ __forceinline__ long long sid_or_neg(const void* p, int i, int B, bool is64) {
    if (i >= B) return -1ll;
    return is64 ? ((const long long*)p)[i] : (long long)((const int*)p)[i];
}

// Sense-reversing global barrier (all GRID blocks resident; replay-safe).
__device__ __forceinline__ void gbar() {
    __syncthreads();
    if (threadIdx.x == 0) {
        __threadfence();
        unsigned my = atomicOr(&g_bar_sense, 0u);
        if (atomicAdd(&g_bar_count, 1u) == GRID - 1) {
            atomicExch(&g_bar_count, 0u);
            __threadfence();
            atomicExch(&g_bar_sense, my ^ 1u);
        } else {
            while (atomicOr(&g_bar_sense, 0u) == my) __nanosleep(32);
        }
        __threadfence();
    }
    __syncthreads();
}

__global__ void __launch_bounds__(T, 1)
fused_contrastive(const void* __restrict__ sids, const float* __restrict__ x,
                  float* __restrict__ out, int B, int D) {
    extern __shared__ unsigned char sm[];
    unsigned short* wc  = (unsigned short*)sm;             // [s*32+w]
    int* scnt = (int*)(sm + WCNT_B);                       // [s] totals (all blocks)
    int* off  = scnt + NSUBJ;                              // [s] cross-block excl offset
    int* ii   = off + NSUBJ;                               // encoded s*CAP+slot
    int* jj   = ii + 2 * MAXP;
    int* npn  = jj + 2 * MAXP;
    float* part = (float*)(npn + 4);                       // [32]

    const int tid = threadIdx.x, lane = tid & 31, w = tid >> 5;
    const int b = blockIdx.x;
    const bool is64 = detect64(sids);

    const int e = (B + GRID * T - 1) / (GRID * T);         // elems per thread (1 here)
    const int base = b * e * T + w * e * 32;

    // zero wc
    {
        unsigned int* z = (unsigned int*)wc;
        for (int k = tid; k < WCNT_B / 4; k += T) z[k] = 0u;
    }
    __syncthreads();

    // ---- A1: per-(subject,warp) counts within block ----
    for (int k = 0; k < e; k++) {
        long long v = sid_or_neg(sids, base + k * 32 + lane, B, is64);
        bool valid = v >= 0;
        int s = valid ? (int)v : 0;
        int key = valid ? s : (NSUBJ + lane);
        unsigned mask = __match_any_sync(0xFFFFFFFFu, key);
        if (valid && lane == (__ffs(mask) - 1))
            wc[s * NWARP + w] = (unsigned short)(wc[s * NWARP + w] + __popc(mask));
    }
    __syncthreads();

    // ---- A2: block-local exclusive prefix over warps; publish per-block count ----
    {
        int s = tid;
        int run = 0;
#pragma unroll
        for (int c = 0; c < NWARP; c++) {
            int v = wc[s * NWARP + c];
            wc[s * NWARP + c] = (unsigned short)run;
            run += v;
        }
        g_bcnt[b * NSUBJ + s] = (unsigned)run;             // coalesced
    }

    gbar();

    // ---- B: cross-block prefix + totals (every block keeps scnt) ----
    {
        int s = tid;
        int pre = 0, tot = 0;
#pragma unroll 16
        for (int c = 0; c < GRID; c++) {
            int u = (int)g_bcnt[c * NSUBJ + s];
            tot += u;
            if (c < b) pre += u;
        }
        off[s] = pre;
        scnt[s] = tot;
    }
    __syncthreads();

    // ---- C: order-preserving scatter of first CAP indices to g_gidx ----
    for (int k = 0; k < e; k++) {
        int i = base + k * 32 + lane;
        long long v = sid_or_neg(sids, i, B, is64);
        bool valid = v >= 0;
        int s = valid ? (int)v : 0;
        int key = valid ? s : (NSUBJ + lane);
        unsigned mask = __match_any_sync(0xFFFFFFFFu, key);
        if (valid) {
            int rank = __popc(mask & ((1u << lane) - 1u));
            int cur = wc[s * NWARP + w];                   // all lanes read before leader store
            int slot = off[s] + cur + rank;
            if (lane == (__ffs(mask) - 1))
                wc[s * NWARP + w] = (unsigned short)(cur + __popc(mask));
            if (slot < CAP) g_gidx[s * CAP + slot] = (unsigned)i;
        }
    }
    __syncthreads();

    // ---- arrive; non-loss blocks exit ----
    if (tid == 0) {
        __threadfence();
        atomicAdd(&g_done, 1u);
    }
    if (b >= NLOSS) return;

    if (tid == 0) {
        while (atomicOr(&g_done, 0u) < GRID) __nanosleep(32);
        __threadfence();
    }
    __syncthreads();

    // ---- D1: exact reference pair enumeration (thread 0, smem-only, encoded) ----
    if (tid == 0) {
        int npos = 0, nneg = 0;
        for (int s = 0; s < NSUBJ; s++) {
            int cs = scnt[s];
            if (cs == 0) continue;                         // uniq (sorted ascending)
            int til = cs < CAP ? cs : CAP;
            if (cs >= 2 && npos < MAXP) {
                for (int a = 0; a < til && npos < MAXP; a++)
                    for (int bb = a + 1; bb < til && npos < MAXP; bb++) {
                        ii[npos] = s * CAP + a;
                        jj[npos] = s * CAP + bb;
                        npos++;
                    }
            }
            for (int o = 0; o < NSUBJ; o++) {
                int co = scnt[o];
                if (co == 0) continue;
                if (o == s) continue;                      // python: continue precedes break
                if (nneg >= MAXP) break;
                int tjl = co < CAP ? co : CAP;
                for (int a = 0; a < til && nneg < MAXP; a++)
                    for (int bb = 0; bb < tjl && nneg < MAXP; bb++) {
                        ii[MAXP + nneg] = s * CAP + a;
                        jj[MAXP + nneg] = o * CAP + bb;
                        nneg++;
                    }
            }
            if (npos >= MAXP && nneg >= MAXP) break;
        }
        npn[0] = npos;
        npn[1] = nneg;
    }
    __syncthreads();

    // ---- D2: this block handles pairs p % NLOSS == b; warp per pair ----
    const int npos = npn[0], nneg = npn[1], n = npos + nneg;
    float acc = 0.0f;
    const int nvec = D / 4;                                // D=384 -> 96 float4
    for (int p = b + NLOSS * w; p < n; p += NLOSS * NWARP) {
        int slot = (p < npos) ? p : (MAXP + (p - npos));
        int i = (int)g_gidx[ii[slot]];
        int j = (int)g_gidx[jj[slot]];
        const float4* xi = (const float4*)(x + (long long)i * D);
        const float4* xj = (const float4*)(x + (long long)j * D);
        float sxx = 0.f, syy = 0.f, sxy = 0.f;
        for (int q = lane; q < nvec; q += 32) {
            float4 a = xi[q];
            float4 bq = xj[q];
            sxx += a.x * a.x + a.y * a.y + a.z * a.z + a.w * a.w;
            syy += bq.x * bq.x + bq.y * bq.y + bq.z * bq.z + bq.w * bq.w;
            sxy += a.x * bq.x + a.y * bq.y + a.z * bq.z + a.w * bq.w;
        }
#pragma unroll
        for (int o = 16; o; o >>= 1) {
            sxx += __shfl_xor_sync(0xFFFFFFFFu, sxx, o);
            syy += __shfl_xor_sync(0xFFFFFFFFu, syy, o);
            sxy += __shfl_xor_sync(0xFFFFFFFFu, sxy, o);
        }
        float ni = fmaxf(sqrtf(sxx), 1e-12f);
        float nj = fmaxf(sqrtf(syy), 1e-12f);
        float sc = (sxy / (ni * nj)) * 2.0f;               // / TEMPERATURE (0.5)
        float xs = (p < npos) ? -sc : sc;
        acc += fmaxf(xs, 0.f) + log1pf(expf(-fabsf(xs))); // softplus(xs)
    }

    // acc replicated across lanes -> lane 0's copy IS the warp partial
    if (lane == 0) part[w] = acc;
    __syncthreads();
    if (w == 0) {
        float v = part[lane];
#pragma unroll
        for (int o = 16; o; o >>= 1) v += __shfl_xor_sync(0xFFFFFFFFu, v, o);
        if (lane == 0) {
            atomicAdd(&g_acc, v);
            __threadfence();
            unsigned old = atomicAdd(&g_ldone, 1u);
            if (old == NLOSS - 1) {                        // last loss block
                float total = atomicAdd(&g_acc, 0.0f);     // atomic read
                out[0] = total / (float)n;
                // reset replay state (all participants already past their uses)
                atomicExch(&g_acc, 0.0f);
                atomicExch(&g_ldone, 0u);
                atomicExch(&g_done, 0u);
            }
        }
    }
}

extern "C" void kernel_launch(void* const* d_in, const int* in_sizes, int n_in,
                              void* d_out, int out_size) {
    const float* x = (const float*)d_in[0];   // identity_tokens [B, D] fp32
    const void* sids = d_in[1];               // subject_ids [B]
    int B = in_sizes[1];
    int D = in_sizes[0] / B;

    cudaFuncSetAttribute(fused_contrastive,
                         cudaFuncAttributeMaxDynamicSharedMemorySize, SMEM_TOTAL);

    fused_contrastive<<<GRID, T, SMEM_TOTAL>>>(sids, x, (float*)d_out, B, D);
}

// round 7
// speedup vs baseline: 6.6806x; 1.0520x over previous
#include <cuda_runtime.h>

// Multi-SM fused ContrastiveLoss, one launch, grid=64 + one global barrier.
// R7: (1) loss blocks run the pair enumeration BEFORE waiting on g_done
// (it depends only on scnt, local to every block after phase B; pairs are
// encoded s*CAP+slot handles). (2) pos and neg pair streams are independent
// given scnt -> emitted concurrently by warp 0 / warp 1 thread leaders.

#define NSUBJ 1024
#define NWARP 32
#define MAXP 50
#define CAP 51
#define GRID 64
#define T 1024
#define NLOSS 4

#define WCNT_B (NSUBJ * NWARP * 2)       // 65536
#define SMEM_TOTAL (WCNT_B + 4096 /*scnt*/ + 4096 /*off*/ + 2*MAXP*4*2 + 16 + 128 + 64)

__device__ unsigned g_bar_count = 0;
__device__ unsigned g_bar_sense = 0;
__device__ unsigned g_done = 0;             // phase-C arrival counter
__device__ unsigned g_ldone = 0;            // loss-block completion counter
__device__ float    g_acc = 0.0f;           // loss partial accumulator
__device__ unsigned g_bcnt[GRID * NSUBJ];   // [block][subject]
__device__ unsigned g_gidx[NSUBJ * CAP];    // [subject][slot]

// subject_ids may be int64 or (jax x64-off) int32.
__device__ __forceinline__ bool detect64(const void* p) {
    const long long* q = (const long long*)p;
    bool ok = true;
#pragma unroll
    for (int k = 0; k < 16; k++) {
        long long v = q[k];
        ok = ok && (v >= 0 && v < (long long)NSUBJ);
    }
    return ok;
}

__device__ __forceinline__ long long sid_or_neg(const void* p, int i, int B, bool is64) {
    if (i >= B) return -1ll;
    return is64 ? ((const long long*)p)[i] : (long long)((const int*)p)[i];
}

// Sense-reversing global barrier (all GRID blocks resident; replay-safe).
__device__ __forceinline__ void gbar() {
    __syncthreads();
    if (threadIdx.x == 0) {
        __threadfence();
        unsigned my = atomicOr(&g_bar_sense, 0u);
        if (atomicAdd(&g_bar_count, 1u) == GRID - 1) {
            atomicExch(&g_bar_count, 0u);
            __threadfence();
            atomicExch(&g_bar_sense, my ^ 1u);
        } else {
            while (atomicOr(&g_bar_sense, 0u) == my) __nanosleep(16);
        }
        __threadfence();
    }
    __syncthreads();
}

__global__ void __launch_bounds__(T, 1)
fused_contrastive(const void* __restrict__ sids, const float* __restrict__ x,
                  float* __restrict__ out, int B, int D) {
    extern __shared__ unsigned char sm[];
    unsigned short* wc  = (unsigned short*)sm;             // [s*32+w]
    int* scnt = (int*)(sm + WCNT_B);                       // [s] totals (all blocks)
    int* off  = scnt + NSUBJ;                              // [s] cross-block excl offset
    int* ii   = off + NSUBJ;                               // encoded s*CAP+slot
    int* jj   = ii + 2 * MAXP;
    int* npn  = jj + 2 * MAXP;
    float* part = (float*)(npn + 4);                       // [32]

    const int tid = threadIdx.x, lane = tid & 31, w = tid >> 5;
    const int b = blockIdx.x;
    const bool is64 = detect64(sids);

    const int e = (B + GRID * T - 1) / (GRID * T);         // elems per thread (1 here)
    const int base = b * e * T + w * e * 32;

    // zero wc
    {
        unsigned int* z = (unsigned int*)wc;
        for (int k = tid; k < WCNT_B / 4; k += T) z[k] = 0u;
    }
    __syncthreads();

    // ---- A1: per-(subject,warp) counts within block ----
    for (int k = 0; k < e; k++) {
        long long v = sid_or_neg(sids, base + k * 32 + lane, B, is64);
        bool valid = v >= 0;
        int s = valid ? (int)v : 0;
        int key = valid ? s : (NSUBJ + lane);
        unsigned mask = __match_any_sync(0xFFFFFFFFu, key);
        if (valid && lane == (__ffs(mask) - 1))
            wc[s * NWARP + w] = (unsigned short)(wc[s * NWARP + w] + __popc(mask));
    }
    __syncthreads();

    // ---- A2: block-local exclusive prefix over warps; publish per-block count ----
    {
        int s = tid;
        int run = 0;
#pragma unroll
        for (int c = 0; c < NWARP; c++) {
            int v = wc[s * NWARP + c];
            wc[s * NWARP + c] = (unsigned short)run;
            run += v;
        }
        g_bcnt[b * NSUBJ + s] = (unsigned)run;             // coalesced
    }

    gbar();

    // ---- B: cross-block prefix + totals (every block keeps scnt) ----
    {
        int s = tid;
        int pre = 0, tot = 0;
#pragma unroll 16
        for (int c = 0; c < GRID; c++) {
            int u = (int)g_bcnt[c * NSUBJ + s];
            tot += u;
            if (c < b) pre += u;
        }
        off[s] = pre;
        scnt[s] = tot;
    }
    __syncthreads();

    // ---- C: order-preserving scatter of first CAP indices to g_gidx ----
    for (int k = 0; k < e; k++) {
        int i = base + k * 32 + lane;
        long long v = sid_or_neg(sids, i, B, is64);
        bool valid = v >= 0;
        int s = valid ? (int)v : 0;
        int key = valid ? s : (NSUBJ + lane);
        unsigned mask = __match_any_sync(0xFFFFFFFFu, key);
        if (valid) {
            int rank = __popc(mask & ((1u << lane) - 1u));
            int cur = wc[s * NWARP + w];                   // all lanes read before leader store
            int slot = off[s] + cur + rank;
            if (lane == (__ffs(mask) - 1))
                wc[s * NWARP + w] = (unsigned short)(cur + __popc(mask));
            if (slot < CAP) g_gidx[s * CAP + slot] = (unsigned)i;
        }
    }
    __syncthreads();

    // ---- arrive; non-loss blocks exit ----
    if (tid == 0) {
        __threadfence();
        atomicAdd(&g_done, 1u);
    }
    if (b >= NLOSS) return;

    // ---- D1 (overlapped with other blocks' C/arrival): pair enumeration.
    // Depends only on scnt. pos stream (thread 0) and neg stream (thread 32)
    // are independent given scnt — see reference loop gating.
    if (tid == 0) {                                        // positive pairs
        int npos = 0;
        for (int s = 0; s < NSUBJ && npos < MAXP; s++) {
            int cs = scnt[s];
            if (cs < 2) continue;
            int til = cs < CAP ? cs : CAP;
            for (int a = 0; a < til && npos < MAXP; a++)
                for (int bb = a + 1; bb < til && npos < MAXP; bb++) {
                    ii[npos] = s * CAP + a;
                    jj[npos] = s * CAP + bb;
                    npos++;
                }
        }
        npn[0] = npos;
    }
    if (tid == 32) {                                       // negative pairs
        int nneg = 0;
        for (int s = 0; s < NSUBJ && nneg < MAXP; s++) {
            int cs = scnt[s];
            if (cs == 0) continue;
            int til = cs < CAP ? cs : CAP;
            for (int o = 0; o < NSUBJ; o++) {
                int co = scnt[o];
                if (co == 0) continue;
                if (o == s) continue;                      // python: continue precedes break
                if (nneg >= MAXP) break;
                int tjl = co < CAP ? co : CAP;
                for (int a = 0; a < til && nneg < MAXP; a++)
                    for (int bb = 0; bb < tjl && nneg < MAXP; bb++) {
                        ii[MAXP + nneg] = s * CAP + a;
                        jj[MAXP + nneg] = o * CAP + bb;
                        nneg++;
                    }
            }
        }
        npn[1] = nneg;
    }

    // ---- wait for all scatters to be visible ----
    if (tid == 0) {
        while (atomicOr(&g_done, 0u) < GRID) __nanosleep(16);
        __threadfence();
    }
    __syncthreads();

    // ---- D2: this block handles pairs p % NLOSS == b; warp per pair ----
    const int npos = npn[0], nneg = npn[1], n = npos + nneg;
    float acc = 0.0f;
    const int nvec = D / 4;                                // D=384 -> 96 float4
    for (int p = b + NLOSS * w; p < n; p += NLOSS * NWARP) {
        int slot = (p < npos) ? p : (MAXP + (p - npos));
        int i = (int)g_gidx[ii[slot]];
        int j = (int)g_gidx[jj[slot]];
        const float4* xi = (const float4*)(x + (long long)i * D);
        const float4* xj = (const float4*)(x + (long long)j * D);
        float sxx = 0.f, syy = 0.f, sxy = 0.f;
        for (int q = lane; q < nvec; q += 32) {
            float4 a = xi[q];
            float4 bq = xj[q];
            sxx += a.x * a.x + a.y * a.y + a.z * a.z + a.w * a.w;
            syy += bq.x * bq.x + bq.y * bq.y + bq.z * bq.z + bq.w * bq.w;
            sxy += a.x * bq.x + a.y * bq.y + a.z * bq.z + a.w * bq.w;
        }
#pragma unroll
        for (int o = 16; o; o >>= 1) {
            sxx += __shfl_xor_sync(0xFFFFFFFFu, sxx, o);
            syy += __shfl_xor_sync(0xFFFFFFFFu, syy, o);
            sxy += __shfl_xor_sync(0xFFFFFFFFu, sxy, o);
        }
        float ni = fmaxf(sqrtf(sxx), 1e-12f);
        float nj = fmaxf(sqrtf(syy), 1e-12f);
        float sc = (sxy / (ni * nj)) * 2.0f;               // / TEMPERATURE (0.5)
        float xs = (p < npos) ? -sc : sc;
        acc += fmaxf(xs, 0.f) + log1pf(expf(-fabsf(xs))); // softplus(xs)
    }

    // acc replicated across lanes -> lane 0's copy IS the warp partial
    if (lane == 0) part[w] = acc;
    __syncthreads();
    if (w == 0) {
        float v = part[lane];
#pragma unroll
        for (int o = 16; o; o >>= 1) v += __shfl_xor_sync(0xFFFFFFFFu, v, o);
        if (lane == 0) {
            atomicAdd(&g_acc, v);
            __threadfence();
            unsigned old = atomicAdd(&g_ldone, 1u);
            if (old == NLOSS - 1) {                        // last loss block
                float total = atomicAdd(&g_acc, 0.0f);     // atomic read
                out[0] = total / (float)n;
                // reset replay state (all participants already past their uses)
                atomicExch(&g_acc, 0.0f);
                atomicExch(&g_ldone, 0u);
                atomicExch(&g_done, 0u);
            }
        }
    }
}

extern "C" void kernel_launch(void* const* d_in, const int* in_sizes, int n_in,
                              void* d_out, int out_size) {
    const float* x = (const float*)d_in[0];   // identity_tokens [B, D] fp32
    const void* sids = d_in[1];               // subject_ids [B]
    int B = in_sizes[1];
    int D = in_sizes[0] / B;

    cudaFuncSetAttribute(fused_contrastive,
                         cudaFuncAttributeMaxDynamicSharedMemorySize, SMEM_TOTAL);

    fused_contrastive<<<GRID, T, SMEM_TOTAL>>>(sids, x, (float*)d_out, B, D);
}

// round 8
// speedup vs baseline: 6.9729x; 1.0437x over previous
#include <cuda_runtime.h>

// Multi-SM fused ContrastiveLoss, one launch, grid=64.
// R8: atomic barriers replaced by epoch-versioned per-block flags with
// parallel per-thread polling (no ATOMG chains, no nanosleep quantization).
// Flags are written only by their owning block -> epoch = old+1 is replay-safe
// (monotone across graph replays, no reset required).

#define NSUBJ 1024
#define NWARP 32
#define MAXP 50
#define CAP 51
#define GRID 64
#define T 1024
#define NLOSS 4

#define WCNT_B (NSUBJ * NWARP * 2)       // 65536
#define SMEM_TOTAL (WCNT_B + 4096 /*scnt*/ + 4096 /*off*/ + 2*MAXP*4*2 + 16 + 128 + 64)

__device__ volatile unsigned g_flagA[GRID];   // after per-block counts published
__device__ volatile unsigned g_flagC[GRID];   // after scatter done
__device__ volatile unsigned g_flagL[NLOSS];  // after loss partial published
__device__ float g_part[NLOSS];               // per-loss-block partial sums
__device__ unsigned g_bcnt[GRID * NSUBJ];     // [block][subject]
__device__ unsigned g_gidx[NSUBJ * CAP];      // [subject][slot]

// subject_ids may be int64 or (jax x64-off) int32.
__device__ __forceinline__ bool detect64(const void* p) {
    const long long* q = (const long long*)p;
    bool ok = true;
#pragma unroll
    for (int k = 0; k < 16; k++) {
        long long v = q[k];
        ok = ok && (v >= 0 && v < (long long)NSUBJ);
    }
    return ok;
}

__device__ __forceinline__ long long sid_or_neg(const void* p, int i, int B, bool is64) {
    if (i >= B) return -1ll;
    return is64 ? ((const long long*)p)[i] : (long long)((const int*)p)[i];
}

__global__ void __launch_bounds__(T, 1)
fused_contrastive(const void* __restrict__ sids, const float* __restrict__ x,
                  float* __restrict__ out, int B, int D) {
    extern __shared__ unsigned char sm[];
    unsigned short* wc  = (unsigned short*)sm;             // [s*32+w]
    int* scnt = (int*)(sm + WCNT_B);                       // [s] totals (all blocks)
    int* off  = scnt + NSUBJ;                              // [s] cross-block excl offset
    int* ii   = off + NSUBJ;                               // encoded s*CAP+slot
    int* jj   = ii + 2 * MAXP;
    int* npn  = jj + 2 * MAXP;
    float* part = (float*)(npn + 4);                       // [32]

    const int tid = threadIdx.x, lane = tid & 31, w = tid >> 5;
    const int b = blockIdx.x;
    const bool is64 = detect64(sids);

    // per-launch epoch: my own flag (only this block writes it) + 1.
    const unsigned epoch = g_flagA[b] + 1u;

    const int e = (B + GRID * T - 1) / (GRID * T);         // elems per thread (1 here)
    const int base = b * e * T + w * e * 32;

    // zero wc
    {
        unsigned int* z = (unsigned int*)wc;
        for (int k = tid; k < WCNT_B / 4; k += T) z[k] = 0u;
    }
    __syncthreads();

    // ---- A1: per-(subject,warp) counts within block ----
    for (int k = 0; k < e; k++) {
        long long v = sid_or_neg(sids, base + k * 32 + lane, B, is64);
        bool valid = v >= 0;
        int s = valid ? (int)v : 0;
        int key = valid ? s : (NSUBJ + lane);
        unsigned mask = __match_any_sync(0xFFFFFFFFu, key);
        if (valid && lane == (__ffs(mask) - 1))
            wc[s * NWARP + w] = (unsigned short)(wc[s * NWARP + w] + __popc(mask));
    }
    __syncthreads();

    // ---- A2: block-local exclusive prefix over warps; publish per-block count ----
    {
        int s = tid;
        int run = 0;
#pragma unroll
        for (int c = 0; c < NWARP; c++) {
            int v = wc[s * NWARP + c];
            wc[s * NWARP + c] = (unsigned short)run;
            run += v;
        }
        g_bcnt[b * NSUBJ + s] = (unsigned)run;             // coalesced
    }

    // ---- flag barrier A: publish, then parallel-poll all blocks ----
    __syncthreads();
    if (tid == 0) {
        __threadfence();
        g_flagA[b] = epoch;
    }
    for (int t = tid; t < GRID; t += T)
        while (g_flagA[t] < epoch) { }
    __syncthreads();
    __threadfence();

    // ---- B: cross-block prefix + totals (every block keeps scnt) ----
    {
        int s = tid;
        int pre = 0, tot = 0;
#pragma unroll 16
        for (int c = 0; c < GRID; c++) {
            int u = (int)g_bcnt[c * NSUBJ + s];
            tot += u;
            if (c < b) pre += u;
        }
        off[s] = pre;
        scnt[s] = tot;
    }
    __syncthreads();

    // ---- C: order-preserving scatter of first CAP indices to g_gidx ----
    for (int k = 0; k < e; k++) {
        int i = base + k * 32 + lane;
        long long v = sid_or_neg(sids, i, B, is64);
        bool valid = v >= 0;
        int s = valid ? (int)v : 0;
        int key = valid ? s : (NSUBJ + lane);
        unsigned mask = __match_any_sync(0xFFFFFFFFu, key);
        if (valid) {
            int rank = __popc(mask & ((1u << lane) - 1u));
            int cur = wc[s * NWARP + w];                   // all lanes read before leader store
            int slot = off[s] + cur + rank;
            if (lane == (__ffs(mask) - 1))
                wc[s * NWARP + w] = (unsigned short)(cur + __popc(mask));
            if (slot < CAP) g_gidx[s * CAP + slot] = (unsigned)i;
        }
    }
    __syncthreads();

    // ---- publish C completion; non-loss blocks exit ----
    if (tid == 0) {
        __threadfence();
        g_flagC[b] = epoch;
    }
    if (b >= NLOSS) return;

    // ---- D1 (overlapped with other blocks' C): pair enumeration from scnt.
    // pos stream (thread 0) and neg stream (thread 32) are independent given scnt.
    if (tid == 0) {                                        // positive pairs
        int npos = 0;
        for (int s = 0; s < NSUBJ && npos < MAXP; s++) {
            int cs = scnt[s];
            if (cs < 2) continue;
            int til = cs < CAP ? cs : CAP;
            for (int a = 0; a < til && npos < MAXP; a++)
                for (int bb = a + 1; bb < til && npos < MAXP; bb++) {
                    ii[npos] = s * CAP + a;
                    jj[npos] = s * CAP + bb;
                    npos++;
                }
        }
        npn[0] = npos;
    }
    if (tid == 32) {                                       // negative pairs
        int nneg = 0;
        for (int s = 0; s < NSUBJ && nneg < MAXP; s++) {
            int cs = scnt[s];
            if (cs == 0) continue;
            int til = cs < CAP ? cs : CAP;
            for (int o = 0; o < NSUBJ; o++) {
                int co = scnt[o];
                if (co == 0) continue;
                if (o == s) continue;                      // python: continue precedes break
                if (nneg >= MAXP) break;
                int tjl = co < CAP ? co : CAP;
                for (int a = 0; a < til && nneg < MAXP; a++)
                    for (int bb = 0; bb < tjl && nneg < MAXP; bb++) {
                        ii[MAXP + nneg] = s * CAP + a;
                        jj[MAXP + nneg] = o * CAP + bb;
                        nneg++;
                    }
            }
        }
        npn[1] = nneg;
    }

    // ---- wait for all scatters (parallel flag poll) ----
    for (int t = tid; t < GRID; t += T)
        while (g_flagC[t] < epoch) { }
    __syncthreads();
    __threadfence();

    // ---- D2: this block handles pairs p % NLOSS == b; warp per pair ----
    const int npos = npn[0], nneg = npn[1], n = npos + nneg;
    float acc = 0.0f;
    const int nvec = D / 4;                                // D=384 -> 96 float4
    for (int p = b + NLOSS * w; p < n; p += NLOSS * NWARP) {
        int slot = (p < npos) ? p : (MAXP + (p - npos));
        int i = (int)g_gidx[ii[slot]];
        int j = (int)g_gidx[jj[slot]];
        const float4* xi = (const float4*)(x + (long long)i * D);
        const float4* xj = (const float4*)(x + (long long)j * D);
        float sxx = 0.f, syy = 0.f, sxy = 0.f;
        for (int q = lane; q < nvec; q += 32) {
            float4 a = xi[q];
            float4 bq = xj[q];
            sxx += a.x * a.x + a.y * a.y + a.z * a.z + a.w * a.w;
            syy += bq.x * bq.x + bq.y * bq.y + bq.z * bq.z + bq.w * bq.w;
            sxy += a.x * bq.x + a.y * bq.y + a.z * bq.z + a.w * bq.w;
        }
#pragma unroll
        for (int o = 16; o; o >>= 1) {
            sxx += __shfl_xor_sync(0xFFFFFFFFu, sxx, o);
            syy += __shfl_xor_sync(0xFFFFFFFFu, syy, o);
            sxy += __shfl_xor_sync(0xFFFFFFFFu, sxy, o);
        }
        float ni = fmaxf(sqrtf(sxx), 1e-12f);
        float nj = fmaxf(sqrtf(syy), 1e-12f);
        float sc = (sxy / (ni * nj)) * 2.0f;               // / TEMPERATURE (0.5)
        float xs = (p < npos) ? -sc : sc;
        acc += fmaxf(xs, 0.f) + log1pf(expf(-fabsf(xs))); // softplus(xs)
    }

    // acc replicated across lanes -> lane 0's copy IS the warp partial
    if (lane == 0) part[w] = acc;
    __syncthreads();
    if (w == 0) {
        float v = part[lane];
#pragma unroll
        for (int o = 16; o; o >>= 1) v += __shfl_xor_sync(0xFFFFFFFFu, v, o);
        if (lane == 0) {
            g_part[b] = v;
            __threadfence();
            g_flagL[b] = epoch;
        }
    }

    // ---- block 0 combines the NLOSS partials deterministically ----
    if (b == 0) {
        if (tid < NLOSS)
            while (g_flagL[tid] < epoch) { }
        __syncthreads();
        __threadfence();
        if (tid == 0) {
            float tot = 0.0f;
#pragma unroll
            for (int r = 0; r < NLOSS; r++) tot += g_part[r];
            out[0] = tot / (float)n;
        }
    }
}

extern "C" void kernel_launch(void* const* d_in, const int* in_sizes, int n_in,
                              void* d_out, int out_size) {
    const float* x = (const float*)d_in[0];   // identity_tokens [B, D] fp32
    const void* sids = d_in[1];               // subject_ids [B]
    int B = in_sizes[1];
    int D = in_sizes[0] / B;

    cudaFuncSetAttribute(fused_contrastive,
                         cudaFuncAttributeMaxDynamicSharedMemorySize, SMEM_TOTAL);

    fused_contrastive<<<GRID, T, SMEM_TOTAL>>>(sids, x, (float*)d_out, B, D);
}

// round 9
// speedup vs baseline: 7.0580x; 1.0122x over previous
#include <cuda_runtime.h>

// Multi-SM fused ContrastiveLoss, one launch, grid=64, ONE inter-block sync.
// R9: the cross-block prefix barrier is deleted. Each block scatters only
// block-LOCAL per-subject slots (g_lidx[b][s][slot<CAP], u16 local index) and
// per-block counts (g_bcnt16[b][s]); global ordering is reconstructed lazily
// by the 4 loss blocks, per pair handle, via a warp-cooperative prefix scan
// over the 64 per-block counts. sid array is read exactly once per thread.

#define NSUBJ 1024
#define NWARP 32
#define MAXP 50
#define CAP 51
#define GRID 64
#define T 1024
#define NLOSS 4

#define WCNT_B (NSUBJ * NWARP * 2)       // 65536
#define SMEM_TOTAL (WCNT_B + 4096 /*scnt*/ + 2*MAXP*4*2 + 16 + 128 + 64)

__device__ volatile unsigned g_flagA[GRID];   // count+scatter published
__device__ volatile unsigned g_flagL[NLOSS];  // loss partial published
__device__ float g_part[NLOSS];               // per-loss-block partials
__device__ unsigned short g_bcnt16[GRID * NSUBJ];         // [block][subject]
__device__ unsigned short g_lidx[GRID * NSUBJ * CAP];     // [block][subject][slot] local idx

// subject_ids may be int64 or (jax x64-off) int32: one broadcast load + vote.
__device__ __forceinline__ bool detect64(const void* p, int lane) {
    long long v = ((const long long*)p)[lane & 15];
    bool ok = (v >= 0 && v < (long long)NSUBJ);
    return __all_sync(0xFFFFFFFFu, ok);
}

__device__ __forceinline__ long long sid_or_neg(const void* p, int i, int B, bool is64) {
    if (i >= B) return -1ll;
    return is64 ? ((const long long*)p)[i] : (long long)((const int*)p)[i];
}

// Warp-cooperative: map (subject, global slot) -> global element index.
// Lanes hold counts of blocks lane and lane+32; shfl inclusive scan gives the
// cross-block exclusive offsets; exactly one lane's block contains the slot.
__device__ __forceinline__ int resolve_idx(int s, int slot, int lane, int eT) {
    int u0 = (int)g_bcnt16[lane * NSUBJ + s];
    int u1 = (int)g_bcnt16[(lane + 32) * NSUBJ + s];
    int s0 = u0, s1 = u1;
#pragma unroll
    for (int d = 1; d < 32; d <<= 1) {
        int t0 = __shfl_up_sync(0xFFFFFFFFu, s0, d);
        int t1 = __shfl_up_sync(0xFFFFFFFFu, s1, d);
        if (lane >= d) { s0 += t0; s1 += t1; }
    }
    int tot0 = __shfl_sync(0xFFFFFFFFu, s0, 31);
    int e0 = s0 - u0;                 // exclusive offset of block `lane`
    int e1 = tot0 + s1 - u1;          // exclusive offset of block `lane+32`
    int blk = -1, loc = 0;
    if (slot >= e0 && slot < e0 + u0) { blk = lane;      loc = slot - e0; }
    if (slot >= e1 && slot < e1 + u1) { blk = lane + 32; loc = slot - e1; }
    int idx = 0;
    if (blk >= 0)
        idx = blk * eT + (int)g_lidx[(blk * NSUBJ + s) * CAP + loc];
    unsigned m = __ballot_sync(0xFFFFFFFFu, blk >= 0);
    return __shfl_sync(0xFFFFFFFFu, idx, __ffs(m) - 1);
}

__global__ void __launch_bounds__(T, 1)
fused_contrastive(const void* __restrict__ sids, const float* __restrict__ x,
                  float* __restrict__ out, int B, int D) {
    extern __shared__ unsigned char sm[];
    unsigned short* wc  = (unsigned short*)sm;             // [s*32+w]
    int* scnt = (int*)(sm + WCNT_B);                       // [s] totals (loss blocks)
    int* ii   = scnt + NSUBJ;                              // encoded s*CAP+slot
    int* jj   = ii + 2 * MAXP;
    int* npn  = jj + 2 * MAXP;
    float* part = (float*)(npn + 4);                       // [32]

    const int tid = threadIdx.x, lane = tid & 31, w = tid >> 5;
    const int b = blockIdx.x;
    const bool is64 = detect64(sids, lane);
    const unsigned epoch = g_flagA[b] + 1u;                // own flag: replay-safe

    const int e = (B + GRID * T - 1) / (GRID * T);         // 1 for B=65536
    const int eT = e * T;
    const int base = b * eT + w * e * 32;

    // zero wc
    {
        unsigned int* z = (unsigned int*)wc;
        for (int k = tid; k < WCNT_B / 4; k += T) z[k] = 0u;
    }
    __syncthreads();

    // ---- A1: per-(subject,warp) counts; retain k=0 sid in a register ----
    long long v0 = -1ll;
    for (int k = 0; k < e; k++) {
        long long v = sid_or_neg(sids, base + k * 32 + lane, B, is64);
        if (k == 0) v0 = v;
        bool valid = v >= 0;
        int s = valid ? (int)v : 0;
        int key = valid ? s : (NSUBJ + lane);
        unsigned mask = __match_any_sync(0xFFFFFFFFu, key);
        if (valid && lane == (__ffs(mask) - 1))
            wc[s * NWARP + w] = (unsigned short)(wc[s * NWARP + w] + __popc(mask));
    }
    __syncthreads();

    // ---- A2: block-local exclusive prefix over warps; publish block count ----
    {
        int s = tid;
        int run = 0;
#pragma unroll
        for (int c = 0; c < NWARP; c++) {
            int v = wc[s * NWARP + c];
            wc[s * NWARP + c] = (unsigned short)run;
            run += v;
        }
        g_bcnt16[b * NSUBJ + s] = (unsigned short)run;     // coalesced u16
    }
    __syncthreads();

    // ---- A3: block-LOCAL order-preserving scatter (no cross-block offset) ----
    for (int k = 0; k < e; k++) {
        int i = base + k * 32 + lane;
        long long v = (k == 0) ? v0 : sid_or_neg(sids, i, B, is64);
        bool valid = v >= 0;
        int s = valid ? (int)v : 0;
        int key = valid ? s : (NSUBJ + lane);
        unsigned mask = __match_any_sync(0xFFFFFFFFu, key);
        if (valid) {
            int rank = __popc(mask & ((1u << lane) - 1u));
            int cur = wc[s * NWARP + w];                   // all lanes read before leader store
            int slot = cur + rank;                         // LOCAL slot
            if (lane == (__ffs(mask) - 1))
                wc[s * NWARP + w] = (unsigned short)(cur + __popc(mask));
            if (slot < CAP)
                g_lidx[(b * NSUBJ + s) * CAP + slot] = (unsigned short)(i - b * eT);
        }
    }
    __syncthreads();

    // ---- publish; non-loss blocks exit (single sync point in the kernel) ----
    if (tid == 0) {
        __threadfence();
        g_flagA[b] = epoch;
    }
    if (b >= NLOSS) return;

    // ---- wait for all blocks (parallel flag poll) ----
    for (int t = tid; t < GRID; t += T)
        while (g_flagA[t] < epoch) { }
    __syncthreads();
    __threadfence();

    // ---- B: per-subject totals (thread s sums its 64-block column) ----
    {
        int s = tid;
        int tot = 0;
#pragma unroll 16
        for (int c = 0; c < GRID; c++) tot += (int)g_bcnt16[c * NSUBJ + s];
        scnt[s] = tot;
    }
    __syncthreads();

    // ---- D1: reference pair enumeration (pos: thread 0, neg: thread 32;
    //      independent given scnt). Handles are s*CAP + global_slot. ----
    if (tid == 0) {                                        // positive pairs
        int npos = 0;
        for (int s = 0; s < NSUBJ && npos < MAXP; s++) {
            int cs = scnt[s];
            if (cs < 2) continue;
            int til = cs < CAP ? cs : CAP;
            for (int a = 0; a < til && npos < MAXP; a++)
                for (int bb = a + 1; bb < til && npos < MAXP; bb++) {
                    ii[npos] = s * CAP + a;
                    jj[npos] = s * CAP + bb;
                    npos++;
                }
        }
        npn[0] = npos;
    }
    if (tid == 32) {                                       // negative pairs
        int nneg = 0;
        for (int s = 0; s < NSUBJ && nneg < MAXP; s++) {
            int cs = scnt[s];
            if (cs == 0) continue;
            int til = cs < CAP ? cs : CAP;
            for (int o = 0; o < NSUBJ; o++) {
                int co = scnt[o];
                if (co == 0) continue;
                if (o == s) continue;                      // python: continue precedes break
                if (nneg >= MAXP) break;
                int tjl = co < CAP ? co : CAP;
                for (int a = 0; a < til && nneg < MAXP; a++)
                    for (int bb = 0; bb < tjl && nneg < MAXP; bb++) {
                        ii[MAXP + nneg] = s * CAP + a;
                        jj[MAXP + nneg] = o * CAP + bb;
                        nneg++;
                    }
            }
        }
        npn[1] = nneg;
    }
    __syncthreads();

    // ---- D2: warp per pair (p % NLOSS == b); lazy slot resolution + loss ----
    const int npos = npn[0], nneg = npn[1], n = npos + nneg;
    float acc = 0.0f;
    const int nvec = D / 4;                                // D=384 -> 96 float4
    for (int p = b + NLOSS * w; p < n; p += NLOSS * NWARP) {
        int slot = (p < npos) ? p : (MAXP + (p - npos));
        int hi = ii[slot], hj = jj[slot];
        int i = resolve_idx(hi / CAP, hi % CAP, lane, eT);
        int j = resolve_idx(hj / CAP, hj % CAP, lane, eT);
        const float4* xi = (const float4*)(x + (long long)i * D);
        const float4* xj = (const float4*)(x + (long long)j * D);
        float sxx = 0.f, syy = 0.f, sxy = 0.f;
        for (int q = lane; q < nvec; q += 32) {
            float4 a = xi[q];
            float4 bq = xj[q];
            sxx += a.x * a.x + a.y * a.y + a.z * a.z + a.w * a.w;
            syy += bq.x * bq.x + bq.y * bq.y + bq.z * bq.z + bq.w * bq.w;
            sxy += a.x * bq.x + a.y * bq.y + a.z * bq.z + a.w * bq.w;
        }
#pragma unroll
        for (int o = 16; o; o >>= 1) {
            sxx += __shfl_xor_sync(0xFFFFFFFFu, sxx, o);
            syy += __shfl_xor_sync(0xFFFFFFFFu, syy, o);
            sxy += __shfl_xor_sync(0xFFFFFFFFu, sxy, o);
        }
        float ni = fmaxf(sqrtf(sxx), 1e-12f);
        float nj = fmaxf(sqrtf(syy), 1e-12f);
        float sc = (sxy / (ni * nj)) * 2.0f;               // / TEMPERATURE (0.5)
        float xs = (p < npos) ? -sc : sc;
        acc += fmaxf(xs, 0.f) + log1pf(expf(-fabsf(xs))); // softplus(xs)
    }

    // acc replicated across lanes -> lane 0's copy IS the warp partial
    if (lane == 0) part[w] = acc;
    __syncthreads();
    if (w == 0) {
        float v = part[lane];
#pragma unroll
        for (int o = 16; o; o >>= 1) v += __shfl_xor_sync(0xFFFFFFFFu, v, o);
        if (lane == 0) {
            g_part[b] = v;
            __threadfence();
            g_flagL[b] = epoch;
        }
    }

    // ---- block 0 combines the NLOSS partials deterministically ----
    if (b == 0) {
        if (tid < NLOSS)
            while (g_flagL[tid] < epoch) { }
        __syncthreads();
        __threadfence();
        if (tid == 0) {
            float tot = 0.0f;
#pragma unroll
            for (int r = 0; r < NLOSS; r++) tot += g_part[r];
            out[0] = tot / (float)n;
        }
    }
}

extern "C" void kernel_launch(void* const* d_in, const int* in_sizes, int n_in,
                              void* d_out, int out_size) {
    const float* x = (const float*)d_in[0];   // identity_tokens [B, D] fp32
    const void* sids = d_in[1];               // subject_ids [B]
    int B = in_sizes[1];
    int D = in_sizes[0] / B;

    cudaFuncSetAttribute(fused_contrastive,
                         cudaFuncAttributeMaxDynamicSharedMemorySize, SMEM_TOTAL);

    fused_contrastive<<<GRID, T, SMEM_TOTAL>>>(sids, x, (float*)d_out, B, D);
}